// round 14
// baseline (speedup 1.0000x reference)
#include <cuda_runtime.h>
#include <cuda_bf16.h>
#include <math.h>
#include <stdint.h>

// ---------------- problem constants ----------------
#define BB    16
#define SS    16
#define HH    32
#define KVH   8
#define HDIM  128
#define MAXS  4096
#define MROWS 256
#define DK    4096
#define KVLEN 4096

// split-K partial buffer layout
#define PSTR 1572864          // per-half stride (256*6144)
#define QOFF 0
#define KOFF 1048576
#define VOFF 1310720

typedef __nv_bfloat16  bf16;
typedef __nv_bfloat162 bf162;

// ---------------- device scratch ----------------
__device__ float g_Xt[MROWS * DK];      // x, tf32-rounded
__device__ float g_Ct[MROWS * DK];      // ctx, tf32-rounded
__device__ float g_Q [MROWS * 4096];
__device__ float g_Kn[MROWS * 1024];
__device__ float g_Vn[MROWS * 1024];
__device__ float g_Gp[2 * PSTR];        // split-K partials (QKV and Wo reuse)
__device__ float g_pM[2 * 128 * 64], g_pL[2 * 128 * 64];
__device__ float g_pC[2 * 128 * 64 * 128];

// ---------------- PTX helpers ----------------
__device__ __forceinline__ uint32_t smem_u32(const void* p) {
    uint32_t a;
    asm("{ .reg .u64 t; cvta.to.shared.u64 t, %1; cvt.u32.u64 %0, t; }" : "=r"(a) : "l"(p));
    return a;
}
#define LDSM4(r, addr) \
    asm volatile("ldmatrix.sync.aligned.m8n8.x4.shared.b16 {%0,%1,%2,%3}, [%4];" \
        : "=r"((r)[0]), "=r"((r)[1]), "=r"((r)[2]), "=r"((r)[3]) : "r"(addr))
#define LDSM4T(r, addr) \
    asm volatile("ldmatrix.sync.aligned.m8n8.x4.trans.shared.b16 {%0,%1,%2,%3}, [%4];" \
        : "=r"((r)[0]), "=r"((r)[1]), "=r"((r)[2]), "=r"((r)[3]) : "r"(addr))
#define MMA16816(d, a, b0, b1) \
    asm volatile("mma.sync.aligned.m16n8k16.row.col.f32.bf16.bf16.f32 " \
        "{%0,%1,%2,%3}, {%4,%5,%6,%7}, {%8,%9}, {%0,%1,%2,%3};" \
        : "+f"((d)[0]), "+f"((d)[1]), "+f"((d)[2]), "+f"((d)[3]) \
        : "r"((a)[0]), "r"((a)[1]), "r"((a)[2]), "r"((a)[3]), "r"(b0), "r"(b1))
#define MMATF32(d, a, b0, b1) \
    asm volatile("mma.sync.aligned.m16n8k8.row.col.f32.tf32.tf32.f32 " \
        "{%0,%1,%2,%3}, {%4,%5,%6,%7}, {%8,%9}, {%0,%1,%2,%3};" \
        : "+f"((d)[0]), "+f"((d)[1]), "+f"((d)[2]), "+f"((d)[3]) \
        : "r"((a)[0]), "r"((a)[1]), "r"((a)[2]), "r"((a)[3]), "r"(b0), "r"(b1))
#define CP16(dst, src) \
    asm volatile("cp.async.cg.shared.global [%0], [%1], 16;" :: "r"(dst), "l"(src))
#define CP_COMMIT() asm volatile("cp.async.commit_group;" ::: "memory")
#define CP_WAIT0()  asm volatile("cp.async.wait_group 0;" ::: "memory")
#define CP_WAIT1()  asm volatile("cp.async.wait_group 1;" ::: "memory")

__device__ __forceinline__ uint32_t f2tf(float f) {
    uint32_t r;
    asm("cvt.rna.tf32.f32 %0, %1;" : "=r"(r) : "f"(f));
    return r;
}
// hi = truncated-to-bf16 pair (PRMT), lo = bf16-rounded residual pair
__device__ __forceinline__ void split4(float4 v, uint32_t& h01, uint32_t& h23,
                                       uint32_t& l01, uint32_t& l23) {
    uint32_t b0 = __float_as_uint(v.x), b1 = __float_as_uint(v.y);
    uint32_t b2 = __float_as_uint(v.z), b3 = __float_as_uint(v.w);
    h01 = __byte_perm(b0, b1, 0x7632);
    h23 = __byte_perm(b2, b3, 0x7632);
    float r0 = v.x - __uint_as_float(b0 & 0xFFFF0000u);
    float r1 = v.y - __uint_as_float(b1 & 0xFFFF0000u);
    float r2 = v.z - __uint_as_float(b2 & 0xFFFF0000u);
    float r3 = v.w - __uint_as_float(b3 & 0xFFFF0000u);
    asm("cvt.rn.bf16x2.f32 %0, %1, %2;" : "=r"(l01) : "f"(r1), "f"(r0));
    asm("cvt.rn.bf16x2.f32 %0, %1, %2;" : "=r"(l23) : "f"(r3), "f"(r2));
}
__device__ __forceinline__ uint32_t pack_hilo(float a, float b, uint32_t& lo) {
    uint32_t ba = __float_as_uint(a), bb = __float_as_uint(b);
    uint32_t h = __byte_perm(ba, bb, 0x7632);
    float ra = a - __uint_as_float(ba & 0xFFFF0000u);
    float rb = b - __uint_as_float(bb & 0xFFFF0000u);
    asm("cvt.rn.bf16x2.f32 %0, %1, %2;" : "=r"(lo) : "f"(rb), "f"(ra));
    return h;
}

// ---------------- x tf32 pre-rounding ----------------
__global__ void conv_tf32(const float* __restrict__ in, float* __restrict__ outp, int n)
{
    int i = blockIdx.x * blockDim.x + threadIdx.x;
    if (i >= n) return;
    outp[i] = __uint_as_float(f2tf(in[i]));
}

// ---------------- partial-add + RoPE (QKV split-K combine) ----------------
__global__ void rope_add(const float* __restrict__ Gp, const int* __restrict__ spp)
{
    const float* p0 = Gp;
    const float* p1 = Gp + PSTR;
    const int NQP = 524288, NKP = 131072, NVP = 131072;
    int idx = blockIdx.x * blockDim.x + threadIdx.x;
    if (idx >= NQP + NKP + NVP) return;
    const int sp = *spp;

    if (idx < NQP + NKP) {
        float* dst; int nh, i; size_t base;
        if (idx < NQP) { dst = g_Q;  nh = 32; i = idx;       base = QOFF; }
        else           { dst = g_Kn; nh = 8;  i = idx - NQP; base = KOFF; }
        int j = i & 63;
        int h = (i >> 6) % nh;
        int m = i / (64 * nh);
        size_t o = base + ((size_t)m * nh + h) * 128 + 2 * j;
        float xr = p0[o]     + p1[o];
        float xi = p0[o + 1] + p1[o + 1];
        float p     = (float)(sp + (m & 15));
        float theta = powf(10000.0f, -(float)(2 * j) / 128.0f);
        float sn, cs;
        sincosf(p * theta, &sn, &cs);
        size_t od = ((size_t)m * nh + h) * 128 + 2 * j;
        dst[od]     = xr * cs - xi * sn;
        dst[od + 1] = xr * sn + xi * cs;
    } else {
        int vo = (idx - NQP - NKP) * 2;
        size_t o = VOFF + vo;
        g_Vn[vo]     = p0[o]     + p1[o];
        g_Vn[vo + 1] = p0[o + 1] + p1[o + 1];
    }
}

// ---------------- Wo partial add ----------------
__global__ void add_out(const float* __restrict__ Gp, float* __restrict__ outp)
{
    int i = blockIdx.x * blockDim.x + threadIdx.x;
    if (i < MROWS * 4096) outp[i] = Gp[i] + Gp[PSTR + i];
}

// ================= tf32 split-K GEMM (unchanged from R12) =================
#define T_STAGE 27648
#define T_SMEM  (3 * T_STAGE)

__global__ __launch_bounds__(256, 2) void tgemm(
    const float* __restrict__ A,
    const float* __restrict__ W0, int N0, int off0,
    const float* __restrict__ W1, int N1, int off1,
    const float* __restrict__ W2, int N2, int off2,
    float* __restrict__ Gp)
{
    extern __shared__ char smg[];
    const int t = threadIdx.x, w = t >> 5, lane = t & 31;
    const int wm = w >> 2, wn = w & 3;
    const int bm = blockIdx.y * 128;
    const int z  = blockIdx.z;
    const int koff = z * 2048;

    int xt = blockIdx.x;
    const int t0n = N0 >> 6, t1n = N1 >> 6;
    const float* W; int Nseg, bn, coff;
    if (xt < t0n)            { W = W0; Nseg = N0; bn = xt * 64;               coff = off0; }
    else if (xt < t0n + t1n) { W = W1; Nseg = N1; bn = (xt - t0n) * 64;       coff = off1; }
    else                     { W = W2; Nseg = N2; bn = (xt - t0n - t1n) * 64; coff = off2; }
    float* C = Gp + (size_t)z * PSTR + coff;

    auto copy_stage = [&](int slot, int ch) {
        const int k0 = koff + ch * 32;
        char* base = smg + slot * T_STAGE;
#pragma unroll
        for (int j = 0; j < 6; j++) {
            int idx = j * 256 + t;
            if (idx < 1024) {
                int r = idx >> 3, c = idx & 7;
                const float* src = A + (size_t)(bm + r) * DK + k0 + c * 4;
                CP16(smem_u32(base + r * 144 + c * 16), src);
            } else {
                int q = idx - 1024, r = q >> 4, c = q & 15;
                const float* src = W + (size_t)(k0 + r) * Nseg + bn + c * 4;
                CP16(smem_u32(base + 18432 + r * 288 + c * 16), src);
            }
        }
    };

    float acc[4][2][4];
#pragma unroll
    for (int a = 0; a < 4; a++)
#pragma unroll
        for (int bq = 0; bq < 2; bq++)
#pragma unroll
            for (int cix = 0; cix < 4; cix++) acc[a][bq][cix] = 0.f;

    const int NCH = 2048 / 32;
    copy_stage(0, 0); CP_COMMIT();
    copy_stage(1, 1); CP_COMMIT();

    const int lq = lane >> 2, lr = lane & 3;

    for (int ch = 0; ch < NCH; ch++) {
        if (ch + 1 < NCH) { CP_WAIT1(); } else { CP_WAIT0(); }
        __syncthreads();

        if (ch + 2 < NCH) { copy_stage((ch + 2) % 3, ch + 2); CP_COMMIT(); }

        const float* stA = (const float*)(smg + (ch % 3) * T_STAGE);
        const float* stW = (const float*)(smg + (ch % 3) * T_STAGE + 18432);

#pragma unroll
        for (int ks = 0; ks < 4; ks++) {
            uint32_t bf[2][2];
#pragma unroll
            for (int tn = 0; tn < 2; tn++) {
                int col = wn * 16 + tn * 8 + lq;
                int kr = ks * 8 + lr;
                bf[tn][0] = f2tf(stW[kr * 72 + col]);
                bf[tn][1] = f2tf(stW[(kr + 4) * 72 + col]);
            }
#pragma unroll
            for (int mt = 0; mt < 4; mt++) {
                int ar = wm * 64 + mt * 16 + lq;
                int ac = ks * 8 + lr;
                uint32_t af[4];
                af[0] = __float_as_uint(stA[ar * 36 + ac]);
                af[1] = __float_as_uint(stA[(ar + 8) * 36 + ac]);
                af[2] = __float_as_uint(stA[ar * 36 + ac + 4]);
                af[3] = __float_as_uint(stA[(ar + 8) * 36 + ac + 4]);
#pragma unroll
                for (int tn = 0; tn < 2; tn++)
                    MMATF32(acc[mt][tn], af, bf[tn][0], bf[tn][1]);
            }
        }
    }

#pragma unroll
    for (int mt = 0; mt < 4; mt++) {
        int r = bm + wm * 64 + mt * 16 + lq;
#pragma unroll
        for (int tn = 0; tn < 2; tn++) {
            int c = bn + wn * 16 + tn * 8 + lr * 2;
            *(float2*)&C[(size_t)r * Nseg + c]       = make_float2(acc[mt][tn][0], acc[mt][tn][1]);
            *(float2*)&C[(size_t)(r + 8) * Nseg + c] = make_float2(acc[mt][tn][2], acc[mt][tn][3]);
        }
    }
}

// ================= flash attention: single-sync chunk loop =================
// Register-staged KV (LDG), double-buffered bf16 hi/lo K/V tiles.
// smem: Q 0..34816 | Kbuf[2] 34816..69632 | Vbuf[2] 69632..104448 | ml 104448
// each K/V buffer: 32 rows x 272B hi (8704) + lo (8704) = 17408 per stage.
#define AT_QH  0
#define AT_KB  34816
#define AT_VB  69632
#define AT_ML  104448
#define ATTN_SMEM 105472
#define NCHA 64

__global__ __launch_bounds__(256, 2) void attn_kernel(const float* __restrict__ cacheK,
                                                      const float* __restrict__ cacheV,
                                                      const int* __restrict__ spp,
                                                      float* __restrict__ pM,
                                                      float* __restrict__ pL,
                                                      float* __restrict__ pC)
{
    extern __shared__ char sm[];
    char* qh = sm + AT_QH;
    float* mlb = (float*)(sm + AT_ML);

    const int t = threadIdx.x, w = t >> 5, lane = t & 31;
    const int b = blockIdx.x >> 3, kvh = blockIdx.x & 7;
    const int half = blockIdx.y;
    const int pb = half * 128 + blockIdx.x;
    const int kvb = half * 2048;
    const int sp = *spp;
    const int wq = w & 3, gk = w >> 2;

    const uint32_t u_qh = smem_u32(qh);
    const uint32_t u_kb = smem_u32(sm + AT_KB);
    const uint32_t u_vb = smem_u32(sm + AT_VB);

    // register staging: 4 float4 K + 4 float4 V per thread per chunk
    float4 kReg[4], vReg[4];
    auto load_kv = [&](int chunk) {
        const int t0 = kvb + chunk * 32;
#pragma unroll
        for (int j = 0; j < 4; j++) {
            int e = j * 256 + t;
            int r = e >> 5, c4 = e & 31;
            int tk = t0 + r;
            const float* ks = (tk < sp)
                ? cacheK + (((size_t)b * MAXS + tk) * KVH + kvh) * HDIM + c4 * 4
                : g_Kn + (((size_t)b * SS + (tk - sp)) * KVH + kvh) * HDIM + c4 * 4;
            const float* vs = (tk < sp)
                ? cacheV + (((size_t)b * MAXS + tk) * KVH + kvh) * HDIM + c4 * 4
                : g_Vn + (((size_t)b * SS + (tk - sp)) * KVH + kvh) * HDIM + c4 * 4;
            kReg[j] = *(const float4*)ks;
            vReg[j] = *(const float4*)vs;
        }
    };

    load_kv(0);

    // Q load + hi/lo split into smem
#pragma unroll
    for (int j = 0; j < 8; j++) {
        int idx = j * 256 + t;
        int r = idx >> 5, c4 = idx & 31;
        const float4 v = *(const float4*)(g_Q +
            (((size_t)b * SS + (r & 15)) * HH + kvh * 4 + (r >> 4)) * HDIM + c4 * 4);
        uint32_t h01, h23, l01, l23;
        split4(v, h01, h23, l01, l23);
        char* hp = qh + r * 272 + c4 * 8;
        *(uint2*)(hp)         = make_uint2(h01, h23);
        *(uint2*)(hp + 17408) = make_uint2(l01, l23);
    }

    const int r0 = wq * 16 + (lane >> 2);
    const int r1 = r0 + 8;
    float mA = __int_as_float(0xff800000), mB = mA;
    float lA = 0.f, lB = 0.f;

    float oacc[16][4];
#pragma unroll
    for (int nt = 0; nt < 16; nt++)
#pragma unroll
        for (int cix = 0; cix < 4; cix++) oacc[nt][cix] = 0.f;

    const float scale = 0.08838834764831845f;
    const uint32_t a_lane = (lane & 15) * 272 + (lane >> 4) * 16;
    const uint32_t b_row  = (lane & 7) + ((lane >> 4) << 3);
    const uint32_t b_col  = ((lane >> 3) & 1) * 16;

    for (int ch = 0; ch < NCHA; ch++) {
        const uint32_t kbuf = u_kb + (ch & 1) * 17408;
        const uint32_t vbuf = u_vb + (ch & 1) * 17408;

        // deposit staged regs -> bf16 hi/lo tiles (double-buffered; no pre-sync needed)
#pragma unroll
        for (int j = 0; j < 4; j++) {
            int e = j * 256 + t;
            int r = e >> 5, c4 = e & 31;
            uint32_t h01, h23, l01, l23;
            split4(kReg[j], h01, h23, l01, l23);
            char* hp = sm + AT_KB + (ch & 1) * 17408 + r * 272 + c4 * 8;
            *(uint2*)(hp)        = make_uint2(h01, h23);
            *(uint2*)(hp + 8704) = make_uint2(l01, l23);
            split4(vReg[j], h01, h23, l01, l23);
            hp = sm + AT_VB + (ch & 1) * 17408 + r * 272 + c4 * 8;
            *(uint2*)(hp)        = make_uint2(h01, h23);
            *(uint2*)(hp + 8704) = make_uint2(l01, l23);
        }
        __syncthreads();                    // the ONLY barrier per chunk

        if (ch + 1 < NCHA) load_kv(ch + 1); // LDG latency hidden by MMA phase

        // ---- S = Q K^T, 3 independent accumulator sets ----
        float aHH[2][4], aHL[2][4], aLH[2][4];
#pragma unroll
        for (int tn = 0; tn < 2; tn++)
#pragma unroll
            for (int cix = 0; cix < 4; cix++) {
                aHH[tn][cix] = 0.f; aHL[tn][cix] = 0.f; aLH[tn][cix] = 0.f;
            }

        const uint32_t kb = kbuf + (gk * 16 + b_row) * 272 + b_col;
#pragma unroll
        for (int ks = 0; ks < 8; ks++) {
            const int ko = ks * 32;
            uint32_t bh_[4], bl_[4];
            LDSM4(bh_, kb + ko);
            LDSM4(bl_, kb + ko + 8704);
            uint32_t aa = u_qh + (wq * 16) * 272 + a_lane + ko;
            uint32_t ah_[4], al_[4];
            LDSM4(ah_, aa);
            LDSM4(al_, aa + 17408);
#pragma unroll
            for (int tn = 0; tn < 2; tn++) {
                MMA16816(aHH[tn], ah_, bh_[tn * 2], bh_[tn * 2 + 1]);
                MMA16816(aHL[tn], ah_, bl_[tn * 2], bl_[tn * 2 + 1]);
                MMA16816(aLH[tn], al_, bh_[tn * 2], bh_[tn * 2 + 1]);
            }
        }

        float s00 = (aHH[0][0] + aHL[0][0] + aLH[0][0]) * scale;
        float s01 = (aHH[0][1] + aHL[0][1] + aLH[0][1]) * scale;
        float s02 = (aHH[1][0] + aHL[1][0] + aLH[1][0]) * scale;
        float s03 = (aHH[1][1] + aHL[1][1] + aLH[1][1]) * scale;
        float s10 = (aHH[0][2] + aHL[0][2] + aLH[0][2]) * scale;
        float s11 = (aHH[0][3] + aHL[0][3] + aLH[0][3]) * scale;
        float s12 = (aHH[1][2] + aHL[1][2] + aLH[1][2]) * scale;
        float s13 = (aHH[1][3] + aHL[1][3] + aLH[1][3]) * scale;

        float mx0 = fmaxf(fmaxf(s00, s01), fmaxf(s02, s03));
        float mx1 = fmaxf(fmaxf(s10, s11), fmaxf(s12, s13));
#pragma unroll
        for (int o = 1; o <= 2; o <<= 1) {
            mx0 = fmaxf(mx0, __shfl_xor_sync(0xffffffffu, mx0, o));
            mx1 = fmaxf(mx1, __shfl_xor_sync(0xffffffffu, mx1, o));
        }
        float m0n = fmaxf(mA, mx0), m1n = fmaxf(mB, mx1);
        float c0 = __expf(mA - m0n), c1 = __expf(mB - m1n);

        float e00 = __expf(s00 - m0n), e01 = __expf(s01 - m0n);
        float e02 = __expf(s02 - m0n), e03 = __expf(s03 - m0n);
        float e10 = __expf(s10 - m1n), e11 = __expf(s11 - m1n);
        float e12 = __expf(s12 - m1n), e13 = __expf(s13 - m1n);

        float sum0 = e00 + e01 + e02 + e03;
        float sum1 = e10 + e11 + e12 + e13;
#pragma unroll
        for (int o = 1; o <= 2; o <<= 1) {
            sum0 += __shfl_xor_sync(0xffffffffu, sum0, o);
            sum1 += __shfl_xor_sync(0xffffffffu, sum1, o);
        }
        lA = lA * c0 + sum0;  mA = m0n;
        lB = lB * c1 + sum1;  mB = m1n;

        uint32_t ph_[4], pl_[4];
        ph_[0] = pack_hilo(e00, e01, pl_[0]);
        ph_[1] = pack_hilo(e10, e11, pl_[1]);
        ph_[2] = pack_hilo(e02, e03, pl_[2]);
        ph_[3] = pack_hilo(e12, e13, pl_[3]);

#pragma unroll
        for (int nt = 0; nt < 16; nt++) {
            oacc[nt][0] *= c0; oacc[nt][1] *= c0;
            oacc[nt][2] *= c1; oacc[nt][3] *= c1;
        }

        // ---- O += P V ----
        const uint32_t vb = vbuf + (gk * 16 + (lane & 15)) * 272 + (lane >> 4) * 16;
#pragma unroll
        for (int nc = 0; nc < 8; nc++) {
            uint32_t va = vb + nc * 32;
            uint32_t vbh[4], vbl[4];
            LDSM4T(vbh, va);
            LDSM4T(vbl, va + 8704);
#pragma unroll
            for (int sub = 0; sub < 2; sub++) {
                int nt = nc * 2 + sub;
                MMA16816(oacc[nt], ph_, vbh[sub * 2], vbh[sub * 2 + 1]);
                MMA16816(oacc[nt], ph_, vbl[sub * 2], vbl[sub * 2 + 1]);
                MMA16816(oacc[nt], pl_, vbh[sub * 2], vbh[sub * 2 + 1]);
            }
        }
    }

    // ---- epilogue: merge k-groups (rowbuf reuses the Q area), write partials ----
    __syncthreads();
    float* rowbuf = (float*)qh;              // 64*128*4 = 32768 <= 34816
    if ((lane & 3) == 0) {
        mlb[(gk * 64 + r0) * 2 + 0] = mA;  mlb[(gk * 64 + r0) * 2 + 1] = lA;
        mlb[(gk * 64 + r1) * 2 + 0] = mB;  mlb[(gk * 64 + r1) * 2 + 1] = lB;
    }
    if (gk == 1) {
#pragma unroll
        for (int nt = 0; nt < 16; nt++) {
            int c = nt * 8 + (lane & 3) * 2;
            *(float2*)&rowbuf[r0 * 128 + c] = make_float2(oacc[nt][0], oacc[nt][1]);
            *(float2*)&rowbuf[r1 * 128 + c] = make_float2(oacc[nt][2], oacc[nt][3]);
        }
    }
    __syncthreads();
    if (gk == 0) {
        float m1r0 = mlb[(64 + r0) * 2 + 0], l1r0 = mlb[(64 + r0) * 2 + 1];
        float m1r1 = mlb[(64 + r1) * 2 + 0], l1r1 = mlb[(64 + r1) * 2 + 1];
        float M0 = fmaxf(mA, m1r0), M1 = fmaxf(mB, m1r1);
        float w00 = __expf(mA - M0), w01 = __expf(m1r0 - M0);
        float w10 = __expf(mB - M1), w11 = __expf(m1r1 - M1);
        float L0 = lA * w00 + l1r0 * w01;
        float L1 = lB * w10 + l1r1 * w11;
#pragma unroll
        for (int nt = 0; nt < 16; nt++) {
            int c = nt * 8 + (lane & 3) * 2;
            float2 o1a = *(float2*)&rowbuf[r0 * 128 + c];
            float2 o1b = *(float2*)&rowbuf[r1 * 128 + c];
            *(float2*)&pC[((size_t)pb * 64 + r0) * 128 + c] =
                make_float2(oacc[nt][0] * w00 + o1a.x * w01,
                            oacc[nt][1] * w00 + o1a.y * w01);
            *(float2*)&pC[((size_t)pb * 64 + r1) * 128 + c] =
                make_float2(oacc[nt][2] * w10 + o1b.x * w11,
                            oacc[nt][3] * w10 + o1b.y * w11);
        }
        if ((lane & 3) == 0) {
            pM[pb * 64 + r0] = M0;  pL[pb * 64 + r0] = L0;
            pM[pb * 64 + r1] = M1;  pL[pb * 64 + r1] = L1;
        }
    }
}

// ---------------- combine halves -> tf32-rounded fp32 ctx ----------------
__global__ void combine_kernel(const float* __restrict__ pM, const float* __restrict__ pL,
                               const float* __restrict__ pC, float* __restrict__ Ct)
{
    const int bq  = blockIdx.x;
    const int b   = bq >> 3;
    const int kvh = bq & 7;
    const int t   = threadIdx.x;

    for (int idx = t; idx < 64 * 128; idx += 256) {
        int r = idx >> 7;
        int d = idx & 127;
        float m0 = pM[bq * 64 + r],         m1 = pM[(128 + bq) * 64 + r];
        float l0 = pL[bq * 64 + r],         l1 = pL[(128 + bq) * 64 + r];
        float m  = fmaxf(m0, m1);
        float w0 = __expf(m0 - m), w1 = __expf(m1 - m);
        float l  = l0 * w0 + l1 * w1;
        float c0 = pC[((size_t)bq * 64 + r) * 128 + d];
        float c1 = pC[((size_t)(128 + bq) * 64 + r) * 128 + d];
        float v  = (c0 * w0 + c1 * w1) / l;

        int rep = r >> 4, s = r & 15;
        size_t o = ((size_t)(b * SS + s) * HH + kvh * 4 + rep) * HDIM + d;
        Ct[o] = __uint_as_float(f2tf(v));
    }
}

// ---------------- launch ----------------
extern "C" void kernel_launch(void* const* d_in, const int* in_sizes, int n_in,
                              void* d_out, int out_size)
{
    const float* x      = (const float*)d_in[0];
    const float* Wq     = (const float*)d_in[1];
    const float* Wk     = (const float*)d_in[2];
    const float* Wv     = (const float*)d_in[3];
    const float* Wo     = (const float*)d_in[4];
    const float* cacheK = (const float*)d_in[5];
    const float* cacheV = (const float*)d_in[6];
    const int*   spp    = (const int*)  d_in[7];
    float*       out    = (float*)d_out;
    (void)in_sizes; (void)n_in; (void)out_size;

    void *xt, *ct, *gp, *pm, *pl, *pc;
    cudaGetSymbolAddress(&xt, g_Xt);   cudaGetSymbolAddress(&ct, g_Ct);
    cudaGetSymbolAddress(&gp, g_Gp);
    cudaGetSymbolAddress(&pm, g_pM);   cudaGetSymbolAddress(&pl, g_pL);
    cudaGetSymbolAddress(&pc, g_pC);

    cudaFuncSetAttribute(tgemm, cudaFuncAttributeMaxDynamicSharedMemorySize, T_SMEM);
    cudaFuncSetAttribute(attn_kernel, cudaFuncAttributeMaxDynamicSharedMemorySize, ATTN_SMEM);

    dim3 blk(256);
    conv_tf32<<<4096, 256>>>(x, (float*)xt, MROWS * DK);

    tgemm<<<dim3(96, 2, 2), blk, T_SMEM>>>(
        (float*)xt,
        Wq, 4096, QOFF,
        Wk, 1024, KOFF,
        Wv, 1024, VOFF,
        (float*)gp);

    rope_add<<<3072, 256>>>((float*)gp, spp);

    attn_kernel<<<dim3(128, 2), blk, ATTN_SMEM>>>(cacheK, cacheV, spp,
                                                  (float*)pm, (float*)pl, (float*)pc);
    combine_kernel<<<128, blk>>>((float*)pm, (float*)pl, (float*)pc, (float*)ct);

    tgemm<<<dim3(64, 2, 2), blk, T_SMEM>>>(
        (float*)ct,
        Wo, 4096, 0,
        (const float*)0, 0, 0,
        (const float*)0, 0, 0,
        (float*)gp);
    add_out<<<4096, 256>>>((float*)gp, out);
}